// round 4
// baseline (speedup 1.0000x reference)
#include <cuda_runtime.h>
#include <cstdint>

// ---------------------------------------------------------------------------
// SpikingNet, JAX threefry PARTITIONABLE mode:
//   random_bits elem i: bits = y0 ^ y1 of threefry(key, (0, i))
//   split(key,T):       keys[t] = (y0, y1) of threefry(key, (0, t))
// 99 LIF iterations (layer2 t=0..98, layer1/RNG t=0..97), batch 4096.
// 128 CTAs x 256 thr, CTA c owns rows [32c, 32c+32).
// GEMMs: fp32, single accumulator per output, ascending k (FFMA chain).
// Elementwise: explicit __f*_rn intrinsics (no contraction) to match XLA.
// ---------------------------------------------------------------------------

namespace {
constexpr int F   = 784;
constexpr int KC  = 56;    // K-chunk
constexpr int NCH = 14;    // 784/56
constexpr int NP  = 128;   // padded N (H1=100 -> 128)
constexpr int H1  = 100;
constexpr int H2  = 10;

struct Smem {
  float x[32][F];        // persistent input tile        100352 B
  float W[2][KC][NP];    // W1 chunk double buffer        57344 B
  float xi[32][KC];      // gated-input chunk              7168 B
  float outer[32][H1];   // layer1 outputs (delayed)      12800 B
  float W2s[H1][H2];     //                                4000 B
  float outb[32][H2];    //                                1280 B
  unsigned key0[98];
  unsigned key1[98];
};

__device__ __forceinline__ void tf2x32(unsigned k0, unsigned k1,
                                       unsigned x0, unsigned x1,
                                       unsigned& y0, unsigned& y1) {
  unsigned k2 = k0 ^ k1 ^ 0x1BD11BDAu;
#define TFR(r) { x0 += x1; x1 = __funnelshift_l(x1, x1, (r)); x1 ^= x0; }
  x0 += k0; x1 += k1;
  TFR(13) TFR(15) TFR(26) TFR(6)
  x0 += k1; x1 += k2 + 1u;
  TFR(17) TFR(29) TFR(16) TFR(24)
  x0 += k2; x1 += k0 + 2u;
  TFR(13) TFR(15) TFR(26) TFR(6)
  x0 += k0; x1 += k1 + 3u;
  TFR(17) TFR(29) TFR(16) TFR(24)
  x0 += k1; x1 += k2 + 4u;
  TFR(13) TFR(15) TFR(26) TFR(6)
  x0 += k2; x1 += k0 + 5u;
#undef TFR
  y0 = x0; y1 = x1;
}

__device__ __forceinline__ float u01(unsigned bits) {
  return __fadd_rn(__uint_as_float((bits >> 9) | 0x3F800000u), -1.0f);
}

__device__ __forceinline__ void stage_w(const float* __restrict__ gW1,
                                        Smem& sm, int chunk, int buf, int tid) {
  const float* src0 = gW1 + chunk * KC * H1;
  float* dst0 = &sm.W[buf][0][0];
  for (int seg = tid; seg < KC * 25; seg += 256) {   // 25 x 16B per row of 100 f32
    int row = seg / 25, part = seg - row * 25;
    unsigned d = (unsigned)__cvta_generic_to_shared(dst0 + row * NP + part * 4);
    const float* s = src0 + row * H1 + part * 4;
    asm volatile("cp.async.ca.shared.global [%0], [%1], 16;\n" :: "r"(d), "l"(s));
  }
}
}  // namespace

__global__ void __launch_bounds__(256, 1)
snn_kernel(const float* __restrict__ gx, const float* __restrict__ gW1,
           const float* __restrict__ gb1, const float* __restrict__ gW2,
           const float* __restrict__ gb2, float* __restrict__ gout) {
  extern __shared__ char smraw[];
  Smem& sm = *reinterpret_cast<Smem*>(smraw);
  const int tid = threadIdx.x;
  const int tx  = tid & 15;
  const int ty  = tid >> 4;
  const int rA0 = blockIdx.x * 32;

  // ---- stage persistent data -------------------------------------------
  for (int e = tid; e < 32 * (F / 4); e += 256) {
    int r = e / (F / 4), seg = e - r * (F / 4);
    reinterpret_cast<float4*>(&sm.x[r][0])[seg] =
        reinterpret_cast<const float4*>(gx + (size_t)(rA0 + r) * F)[seg];
  }
  for (int e = tid; e < H1 * H2; e += 256) (&sm.W2s[0][0])[e] = gW2[e];
  for (int e = tid; e < 2 * KC * NP; e += 256)
    if ((e & (NP - 1)) >= H1) (&sm.W[0][0][0])[e] = 0.f;   // zero pad cols
  for (int e = tid; e < 32 * H1; e += 256) (&sm.outer[0][0])[e] = 0.f;

  // per-step keys (foldlike split): keys[t] = threefry((0,42), (0, t))
  if (tid < 98) {
    unsigned a0, a1;
    tf2x32(0u, 42u, 0u, (unsigned)tid, a0, a1);
    sm.key0[tid] = a0; sm.key1[tid] = a1;
  }

  // per-thread RNG element map: 7 elements e = tid + 256*u of 32x56 chunk
  unsigned cntb[7]; int xoff[7];
  #pragma unroll
  for (int u = 0; u < 7; ++u) {
    int e = tid + 256 * u;
    int r = e / KC, k = e - r * KC;
    cntb[u] = (unsigned)(rA0 + r) * 784u + (unsigned)k;  // + c*56 per chunk
    xoff[u] = r * F + k;
  }

  // ---- per-thread persistent state --------------------------------------
  float inner1[2][8];
  #pragma unroll
  for (int i = 0; i < 2; ++i)
    #pragma unroll
    for (int q = 0; q < 8; ++q) inner1[i][q] = 0.f;
  float b1r[8];
  #pragma unroll
  for (int q = 0; q < 8; ++q) {
    int j = tx * 8 + q;
    b1r[q] = (j < H1) ? gb1[j] : 0.f;
  }
  const int ra = tid / 10, ja = tid - ra * 10;
  const float b2a = gb2[ja];
  const bool hasb = tid < 64;
  const int rb = (256 + tid) / 10, jb = (256 + tid) - rb * 10;
  const float b2b = hasb ? gb2[jb] : 0.f;
  float i2a = 0.f, i2b = 0.f, acca = 0.f, accb = 0.f;

  // prologue: chunk 0 -> buf 0
  stage_w(gW1, sm, 0, 0, tid);
  asm volatile("cp.async.commit_group;\n");
  asm volatile("cp.async.wait_group 0;\n");
  __syncthreads();

  // ======================= time loop =====================================
  for (int t = 0; t < 99; ++t) {
    // ---- layer2 on DELAYED outer1: single ascending-h FMA chain ----
    {
      float s = 0.f;
      #pragma unroll 5
      for (int h = 0; h < H1; ++h)
        s = fmaf(sm.outer[ra][h], sm.W2s[h][ja], s);
      float exc = __fadd_rn(s, b2a);
      float in2 = __fadd_rn(exc, __fmul_rn(i2a, 0.9f));
      float o2  = __fadd_rn(in2, -1.0f);
      float pen = __fsub_rn(in2, __fmul_rn(1.5f, in2));
      i2a = (o2 > 0.f) ? pen : in2;
      if (t >= 19) acca = __fadd_rn(acca, i2a);
    }
    if (hasb) {
      float s = 0.f;
      #pragma unroll 5
      for (int h = 0; h < H1; ++h)
        s = fmaf(sm.outer[rb][h], sm.W2s[h][jb], s);
      float exc = __fadd_rn(s, b2b);
      float in2 = __fadd_rn(exc, __fmul_rn(i2b, 0.9f));
      float o2  = __fadd_rn(in2, -1.0f);
      float pen = __fsub_rn(in2, __fmul_rn(1.5f, in2));
      i2b = (o2 > 0.f) ? pen : in2;
      if (t >= 19) accb = __fadd_rn(accb, i2b);
    }

    // ---- layer1: RNG-gated GEMM (t < 98) ----
    if (t < 98) {
      const unsigned kk0 = sm.key0[t], kk1 = sm.key1[t];
      float acc[2][8];
      #pragma unroll
      for (int i = 0; i < 2; ++i)
        #pragma unroll
        for (int q = 0; q < 8; ++q) acc[i][q] = 0.f;

      for (int c = 0; c < NCH; ++c) {
        __syncthreads();  // prev GEMM done: xi + peer W-buffer reusable
        stage_w(gW1, sm, (c + 1) % NCH, (c + 1) & 1, tid);
        asm volatile("cp.async.commit_group;\n");

        // xi chunk: partitionable bits = y0 ^ y1, counter (0, i)
        const unsigned coff = (unsigned)(c * KC);
        #pragma unroll
        for (int u = 0; u < 7; ++u) {
          unsigned y0, y1;
          tf2x32(kk0, kk1, 0u, cntb[u] + coff, y0, y1);
          float g = u01(y0 ^ y1);
          (&sm.xi[0][0])[tid + 256 * u] =
              __fmul_rn(g, (&sm.x[0][0])[xoff[u] + c * KC]);
        }
        asm volatile("cp.async.wait_group 1;\n");
        __syncthreads();

        // GEMM: 32 x 128 x 56, per-thread 2x8 tile, ascending k
        const float* Wb = &sm.W[c & 1][0][0];
        const float* xa = &sm.xi[ty][0];
        const float* xb = &sm.xi[16 + ty][0];
        #pragma unroll 2
        for (int k = 0; k < KC; k += 4) {
          float4 a0 = *reinterpret_cast<const float4*>(xa + k);
          float4 a1 = *reinterpret_cast<const float4*>(xb + k);
          float a0v[4] = {a0.x, a0.y, a0.z, a0.w};
          float a1v[4] = {a1.x, a1.y, a1.z, a1.w};
          #pragma unroll
          for (int u = 0; u < 4; ++u) {
            float4 w0 = *reinterpret_cast<const float4*>(Wb + (k + u) * NP + tx * 8);
            float4 w1 = *reinterpret_cast<const float4*>(Wb + (k + u) * NP + tx * 8 + 4);
            acc[0][0] = fmaf(a0v[u], w0.x, acc[0][0]);
            acc[0][1] = fmaf(a0v[u], w0.y, acc[0][1]);
            acc[0][2] = fmaf(a0v[u], w0.z, acc[0][2]);
            acc[0][3] = fmaf(a0v[u], w0.w, acc[0][3]);
            acc[0][4] = fmaf(a0v[u], w1.x, acc[0][4]);
            acc[0][5] = fmaf(a0v[u], w1.y, acc[0][5]);
            acc[0][6] = fmaf(a0v[u], w1.z, acc[0][6]);
            acc[0][7] = fmaf(a0v[u], w1.w, acc[0][7]);
            acc[1][0] = fmaf(a1v[u], w0.x, acc[1][0]);
            acc[1][1] = fmaf(a1v[u], w0.y, acc[1][1]);
            acc[1][2] = fmaf(a1v[u], w0.z, acc[1][2]);
            acc[1][3] = fmaf(a1v[u], w0.w, acc[1][3]);
            acc[1][4] = fmaf(a1v[u], w1.x, acc[1][4]);
            acc[1][5] = fmaf(a1v[u], w1.y, acc[1][5]);
            acc[1][6] = fmaf(a1v[u], w1.z, acc[1][6]);
            acc[1][7] = fmaf(a1v[u], w1.w, acc[1][7]);
          }
        }
      }

      // layer1 LIF epilogue (exact reference op order)
      #pragma unroll
      for (int i = 0; i < 2; ++i) {
        int r = ty + i * 16;
        #pragma unroll
        for (int q = 0; q < 8; ++q) {
          float exc = __fadd_rn(acc[i][q], b1r[q]);
          float in1 = __fadd_rn(exc, __fmul_rn(inner1[i][q], 0.9f));
          float o1  = fmaxf(__fadd_rn(in1, -1.0f), 0.f);
          float pen = __fsub_rn(in1, __fmul_rn(1.5f, in1));
          inner1[i][q] = (o1 > 0.f) ? pen : in1;
          int j = tx * 8 + q;
          if (j < H1) sm.outer[r][j] = o1;
        }
      }
    }
    __syncthreads();  // outer1 published before next step's layer2
  }

  // ---- log_softmax output ----------------------------------------------
  (&sm.outb[0][0])[tid] = acca;
  if (hasb) (&sm.outb[0][0])[256 + tid] = accb;
  __syncthreads();
  if (tid < 32) {
    float v[10], m = -3.4e38f;
    #pragma unroll
    for (int j = 0; j < 10; ++j) { v[j] = sm.outb[tid][j]; m = fmaxf(m, v[j]); }
    float s = 0.f;
    #pragma unroll
    for (int j = 0; j < 10; ++j) s = __fadd_rn(s, expf(__fsub_rn(v[j], m)));
    float l = logf(s);
    #pragma unroll
    for (int j = 0; j < 10; ++j)
      gout[(rA0 + tid) * 10 + j] = __fsub_rn(__fsub_rn(v[j], m), l);
  }
}

extern "C" void kernel_launch(void* const* d_in, const int* in_sizes, int n_in,
                              void* d_out, int out_size) {
  (void)in_sizes; (void)n_in; (void)out_size;
  const float* x  = (const float*)d_in[0];
  const float* W1 = (const float*)d_in[1];
  const float* b1 = (const float*)d_in[2];
  const float* W2 = (const float*)d_in[3];
  const float* b2 = (const float*)d_in[4];
  cudaFuncSetAttribute(snn_kernel, cudaFuncAttributeMaxDynamicSharedMemorySize,
                       (int)sizeof(Smem));
  snn_kernel<<<128, 256, sizeof(Smem)>>>(x, W1, b1, W2, b2, (float*)d_out);
}

// round 5
// speedup vs baseline: 1.0176x; 1.0176x over previous
#include <cuda_runtime.h>
#include <cstdint>

// ---------------------------------------------------------------------------
// SpikingNet, JAX threefry PARTITIONABLE mode (confirmed R4).
// Warp-specialized persistent kernel: 128 CTAs x 512 thr.
//   warps 0-7  : GEMM  32x128x56 per chunk, f32x2 packed FFMA (col pairs)
//   warps 8-15 : threefry RNG producing next chunk's gated inputs (xi)
// xi double-buffered, transposed, value-duplicated {v,v} for direct f32x2 use.
// Arithmetic per output identical to R4 (single ascending-k FMA chain; lane
// rounding of fma.rn.f32x2 == fmaf), so correctness margin is preserved.
// ---------------------------------------------------------------------------

namespace {
constexpr int F   = 784;
constexpr int XP  = 788;   // x pitch in floats: 16B-aligned rows, odd word-stride mod 32
constexpr int KC  = 56;    // K-chunk
constexpr int NCH = 14;    // 784/56
constexpr int NP  = 128;   // padded N (H1=100 -> 128)
constexpr int H1  = 100;
constexpr int H2  = 10;

struct Smem {
  float  x[32][XP];          // persistent input tile      100,864 B
  float  W[2][KC][NP];       // W1 chunk double buffer      57,344 B
  float2 xit[2][KC][32];     // xi, transposed, {v,v} dup   28,672 B
  float  outer[32][H1];      // layer1 outputs (delayed)    12,800 B
  float  W2s[H1][H2];        //                              4,000 B
  float  outb[32][H2];       //                              1,280 B
  unsigned key0[98];
  unsigned key1[98];
};

__device__ __forceinline__ void tf2x32(unsigned k0, unsigned k1,
                                       unsigned x0, unsigned x1,
                                       unsigned& y0, unsigned& y1) {
  unsigned k2 = k0 ^ k1 ^ 0x1BD11BDAu;
#define TFR(r) { x0 += x1; x1 = __funnelshift_l(x1, x1, (r)); x1 ^= x0; }
  x0 += k0; x1 += k1;
  TFR(13) TFR(15) TFR(26) TFR(6)
  x0 += k1; x1 += k2 + 1u;
  TFR(17) TFR(29) TFR(16) TFR(24)
  x0 += k2; x1 += k0 + 2u;
  TFR(13) TFR(15) TFR(26) TFR(6)
  x0 += k0; x1 += k1 + 3u;
  TFR(17) TFR(29) TFR(16) TFR(24)
  x0 += k1; x1 += k2 + 4u;
  TFR(13) TFR(15) TFR(26) TFR(6)
  x0 += k2; x1 += k0 + 5u;
#undef TFR
  y0 = x0; y1 = x1;
}

__device__ __forceinline__ float u01(unsigned bits) {
  return __fadd_rn(__uint_as_float((bits >> 9) | 0x3F800000u), -1.0f);
}

// packed dual FMA: d.lane += a.lane * b.lane  (lane-wise identical to fmaf)
__device__ __forceinline__ void ffma2(unsigned long long& d,
                                      unsigned long long a,
                                      unsigned long long b) {
  asm("fma.rn.f32x2 %0, %1, %2, %0;" : "+l"(d) : "l"(a), "l"(b));
}

__device__ __forceinline__ void lds2u64(unsigned long long& a,
                                        unsigned long long& b, unsigned addr) {
  asm volatile("ld.shared.v2.u64 {%0,%1}, [%2];" : "=l"(a), "=l"(b) : "r"(addr));
}

__device__ __forceinline__ void unpack2(unsigned long long v, float& lo, float& hi) {
  asm("mov.b64 {%0,%1}, %2;" : "=f"(lo), "=f"(hi) : "l"(v));
}

__device__ __forceinline__ void stage_w(const float* __restrict__ gW1,
                                        Smem& sm, int chunk, int buf, int gtid) {
  const float* src0 = gW1 + chunk * KC * H1;
  float* dst0 = &sm.W[buf][0][0];
  for (int seg = gtid; seg < KC * 25; seg += 256) {   // 25 x 16B per row of 100 f32
    int row = seg / 25, part = seg - row * 25;
    unsigned d = (unsigned)__cvta_generic_to_shared(dst0 + row * NP + part * 4);
    const float* s = src0 + row * H1 + part * 4;
    asm volatile("cp.async.ca.shared.global [%0], [%1], 16;\n" :: "r"(d), "l"(s));
  }
}
}  // namespace

__global__ void __launch_bounds__(512, 1)
snn_kernel(const float* __restrict__ gx, const float* __restrict__ gW1,
           const float* __restrict__ gb1, const float* __restrict__ gW2,
           const float* __restrict__ gb2, float* __restrict__ gout) {
  extern __shared__ char smraw[];
  Smem& sm = *reinterpret_cast<Smem*>(smraw);
  const int tid  = threadIdx.x;
  const int rA0  = blockIdx.x * 32;
  const bool isG = tid < 256;          // warps 0-7: GEMM, warps 8-15: RNG

  // ---- stage persistent data -------------------------------------------
  for (int e = tid; e < 32 * (F / 4); e += 512) {
    int r = e / (F / 4), seg = e - r * (F / 4);
    *reinterpret_cast<float4*>(&sm.x[r][seg * 4]) =
        reinterpret_cast<const float4*>(gx + (size_t)(rA0 + r) * F)[seg];
  }
  for (int e = tid; e < H1 * H2; e += 512) (&sm.W2s[0][0])[e] = gW2[e];
  for (int e = tid; e < 32 * H1; e += 512) (&sm.outer[0][0])[e] = 0.f;
  if (tid < 98) {   // foldlike split: keys[t] = threefry((0,42),(0,t))
    unsigned a0, a1;
    tf2x32(0u, 42u, 0u, (unsigned)tid, a0, a1);
    sm.key0[tid] = a0; sm.key1[tid] = a1;
  }
  __syncthreads();

  // ---- GEMM-half persistent state ---------------------------------------
  const int tx = tid & 15;             // col group: cols tx*8 .. tx*8+7
  const int ry = (tid >> 4) & 15;      // row pair:  rows 2ry, 2ry+1
  float inner1E[8], inner1O[8], b1c[8];
  #pragma unroll
  for (int q = 0; q < 8; ++q) {
    inner1E[q] = 0.f; inner1O[q] = 0.f;
    int j = tx * 8 + q;
    b1c[q] = (j < H1) ? gb1[j] : 0.f;
  }
  const unsigned wB0 = (unsigned)__cvta_generic_to_shared(&sm.W[0][0][tx * 8]);
  const unsigned aB0 = (unsigned)__cvta_generic_to_shared(&sm.xit[0][0][2 * ry]);
  constexpr unsigned WBUF = KC * NP * 4;       // bytes per W buffer
  constexpr unsigned ABUF = KC * 32 * 8;       // bytes per xit buffer

  // ---- RNG-half mapping ---------------------------------------------------
  const int rtid = tid - 256;
  const int rr = rtid & 31;            // batch row within tile
  const int kg = rtid >> 5;            // k group: k = kg*7 + i
  const unsigned cbase = (unsigned)(rA0 + rr) * 784u + (unsigned)(kg * 7);
  const float* xrow = &sm.x[rr & 31][0];

  // ---- layer2 state (threads 0..319: r = tid/10, j = tid%10) -------------
  const int ra = tid / 10, ja = tid - ra * 10;
  const bool hasL2 = tid < 320;
  const float b2a = hasL2 ? gb2[ja] : 0.f;
  float i2a = 0.f, acca = 0.f;

  // ---- pipeline prologue --------------------------------------------------
  if (isG) {
    stage_w(gW1, sm, 0, 0, tid);
    asm volatile("cp.async.commit_group;\n");
  } else {
    const unsigned kk0 = sm.key0[0], kk1 = sm.key1[0];
    #pragma unroll
    for (int i = 0; i < 7; ++i) {
      unsigned y0, y1;
      tf2x32(kk0, kk1, 0u, cbase + (unsigned)i, y0, y1);
      float v = __fmul_rn(u01(y0 ^ y1), xrow[kg * 7 + i]);
      sm.xit[0][kg * 7 + i][rr] = make_float2(v, v);
    }
  }
  __syncthreads();

  // ======================= time loop =====================================
  for (int t = 0; t < 99; ++t) {
    // ---- layer2 on DELAYED outer1 (t-1 values) ----
    if (hasL2) {
      float s = 0.f;
      #pragma unroll 5
      for (int h = 0; h < H1; ++h)
        s = fmaf(sm.outer[ra][h], sm.W2s[h][ja], s);
      float exc = __fadd_rn(s, b2a);
      float in2 = __fadd_rn(exc, __fmul_rn(i2a, 0.9f));
      float o2  = __fadd_rn(in2, -1.0f);
      float pen = __fsub_rn(in2, __fmul_rn(1.5f, in2));
      i2a = (o2 > 0.f) ? pen : in2;
      if (t >= 19) acca = __fadd_rn(acca, i2a);
    }

    if (t < 98) {
      if (isG) {
        // ================= GEMM half =================
        unsigned long long accE[4] = {0ull, 0ull, 0ull, 0ull};
        unsigned long long accO[4] = {0ull, 0ull, 0ull, 0ull};
        for (int c = 0; c < NCH; ++c) {
          stage_w(gW1, sm, (c + 1) % NCH, (c + 1) & 1, tid);
          asm volatile("cp.async.commit_group;\n");
          asm volatile("cp.async.wait_group 1;\n");   // W[c] ready

          const unsigned wB = wB0 + (unsigned)(c & 1) * WBUF;
          const unsigned aB = aB0 + (unsigned)(c & 1) * ABUF;
          #pragma unroll 4
          for (int k = 0; k < KC; ++k) {
            unsigned long long aE, aO, w01, w23, w45, w67;
            lds2u64(aE, aO, aB + (unsigned)k * 256u);
            lds2u64(w01, w23, wB + (unsigned)k * 512u);
            lds2u64(w45, w67, wB + (unsigned)k * 512u + 16u);
            ffma2(accE[0], aE, w01); ffma2(accO[0], aO, w01);
            ffma2(accE[1], aE, w23); ffma2(accO[1], aO, w23);
            ffma2(accE[2], aE, w45); ffma2(accO[2], aO, w45);
            ffma2(accE[3], aE, w67); ffma2(accO[3], aO, w67);
          }
          if (c == NCH - 1) {
            // LIF epilogue (exact reference op order), publish outer(t)
            #pragma unroll
            for (int p = 0; p < 4; ++p) {
              float eL, eH, oL, oH;
              unpack2(accE[p], eL, eH);
              unpack2(accO[p], oL, oH);
              float av[4] = {eL, eH, oL, oH};
              #pragma unroll
              for (int h = 0; h < 4; ++h) {
                int q = 2 * p + (h & 1);
                int row = 2 * ry + (h >> 1);
                float* inn = (h >> 1) ? inner1O : inner1E;
                float exc = __fadd_rn(av[h], b1c[q]);
                float in1 = __fadd_rn(exc, __fmul_rn(inn[q], 0.9f));
                float o1  = fmaxf(__fadd_rn(in1, -1.0f), 0.f);
                float pen = __fsub_rn(in1, __fmul_rn(1.5f, in1));
                inn[q] = (o1 > 0.f) ? pen : in1;
                int j = tx * 8 + q;
                if (j < H1) sm.outer[row][j] = o1;
              }
            }
          }
          __syncthreads();   // xi[c+1] ready; outer(t) published at c==13
        }
      } else {
        // ================= RNG half: produce next chunk =================
        for (int c = 0; c < NCH; ++c) {
          int tt = (c < NCH - 1) ? t : t + 1;
          int cc = (c < NCH - 1) ? c + 1 : 0;
          if (tt < 98) {
            const unsigned kk0 = sm.key0[tt], kk1 = sm.key1[tt];
            const unsigned coff = (unsigned)(cc * KC);
            const float* xs = xrow + cc * KC + kg * 7;
            float2* dst = &sm.xit[cc & 1][kg * 7][rr];
            #pragma unroll
            for (int i = 0; i < 7; ++i) {
              unsigned y0, y1;
              tf2x32(kk0, kk1, 0u, cbase + coff + (unsigned)i, y0, y1);
              float v = __fmul_rn(u01(y0 ^ y1), xs[i]);
              dst[i * 32] = make_float2(v, v);
            }
          }
          __syncthreads();
        }
      }
    }
  }

  // ---- log_softmax output ----------------------------------------------
  __syncthreads();
  if (hasL2) (&sm.outb[0][0])[tid] = acca;
  __syncthreads();
  if (tid < 32) {
    float v[10], m = -3.4e38f;
    #pragma unroll
    for (int j = 0; j < 10; ++j) { v[j] = sm.outb[tid][j]; m = fmaxf(m, v[j]); }
    float s = 0.f;
    #pragma unroll
    for (int j = 0; j < 10; ++j) s = __fadd_rn(s, expf(__fsub_rn(v[j], m)));
    float l = logf(s);
    #pragma unroll
    for (int j = 0; j < 10; ++j)
      gout[(rA0 + tid) * 10 + j] = __fsub_rn(__fsub_rn(v[j], m), l);
  }
}

extern "C" void kernel_launch(void* const* d_in, const int* in_sizes, int n_in,
                              void* d_out, int out_size) {
  (void)in_sizes; (void)n_in; (void)out_size;
  const float* x  = (const float*)d_in[0];
  const float* W1 = (const float*)d_in[1];
  const float* b1 = (const float*)d_in[2];
  const float* W2 = (const float*)d_in[3];
  const float* b2 = (const float*)d_in[4];
  cudaFuncSetAttribute(snn_kernel, cudaFuncAttributeMaxDynamicSharedMemorySize,
                       (int)sizeof(Smem));
  snn_kernel<<<128, 512, sizeof(Smem)>>>(x, W1, b1, W2, b2, (float*)d_out);
}

// round 6
// speedup vs baseline: 1.3400x; 1.3168x over previous
#include <cuda_runtime.h>
#include <cstdint>

// ---------------------------------------------------------------------------
// SpikingNet, JAX threefry PARTITIONABLE mode (confirmed R4).
// 128 CTAs x 576 thr, decoupled producer/consumer via named barriers:
//   warps 0-3   (128 thr): GEMM 32x128x56 per chunk (4 rows x 8 cols/thread,
//                FFMA2), W staging (cp.async, swizzled bank-conflict-free
//                layout), LIF-1 epilogue, layer2 + output.
//   warps 4-17  (448 thr): threefry RNG -> gated inputs xi (2-buffer ring).
// Per-output arithmetic identical to R4/R5 (single ascending-k FMA chain).
// ---------------------------------------------------------------------------

namespace {
constexpr int F     = 784;
constexpr int KC    = 56;                 // K-chunk
constexpr int NCH   = 14;                 // 784/56
constexpr int H1    = 100;
constexpr int H2    = 10;
constexpr int XPW   = 788;                // x row pitch (floats), 16B-aligned
constexpr int WROW  = 140;                // swizzled W row pitch (floats)
constexpr int WBUFW = KC * WROW;          // 7840 floats per W buffer
constexpr int AROW  = 34;                 // xit row pitch (float2), 16B-aligned
constexpr int ABUF2 = KC * AROW;          // 1904 float2 per xi buffer
constexpr int NSTEP = 98;                 // layer1 steps
constexpr int NG    = NSTEP * NCH;        // 1372 chunks total
constexpr int TPB   = 576;

struct Smem {
  float    x[32 * XPW];          // 100,864 B
  float    W[2 * WBUFW];         //  62,720 B (swizzled, dbl buffer)
  float2   xit[2 * ABUF2];       //  30,464 B ({v,v} dup, [k][row])
  float    outer[32][H1];        //  12,800 B
  float    inner1[32][H1];       //  12,800 B
  float    W2s[H1][H2];          //   4,000 B
  float    b1s[H1];
  float    b2s[H2];
  float    outb[32][H2];
  unsigned key0[NSTEP], key1[NSTEP];
};                                // ~226 KB total

// W column-group swizzle: group g (8 cols) at word (g/4)*36 + (g%4)*8.
// Bank bases mod 32 = {0,8,16,24, 4,12,20,28, 8,16,24,0, 12,20,28,4}:
// each bank covered exactly 2x -> minimal 2-phase LDS (was 4-way conflict).
__device__ __forceinline__ int woff(int g) { return (g >> 2) * 36 + (g & 3) * 8; }

__device__ __forceinline__ void tf2x32(unsigned k0, unsigned k1,
                                       unsigned x0, unsigned x1,
                                       unsigned& y0, unsigned& y1) {
  unsigned k2 = k0 ^ k1 ^ 0x1BD11BDAu;
#define TFR(r) { x0 += x1; x1 = __funnelshift_l(x1, x1, (r)); x1 ^= x0; }
  x0 += k0; x1 += k1;
  TFR(13) TFR(15) TFR(26) TFR(6)
  x0 += k1; x1 += k2 + 1u;
  TFR(17) TFR(29) TFR(16) TFR(24)
  x0 += k2; x1 += k0 + 2u;
  TFR(13) TFR(15) TFR(26) TFR(6)
  x0 += k0; x1 += k1 + 3u;
  TFR(17) TFR(29) TFR(16) TFR(24)
  x0 += k1; x1 += k2 + 4u;
  TFR(13) TFR(15) TFR(26) TFR(6)
  x0 += k2; x1 += k0 + 5u;
#undef TFR
  y0 = x0; y1 = x1;
}

__device__ __forceinline__ float u01(unsigned bits) {
  return __fadd_rn(__uint_as_float((bits >> 9) | 0x3F800000u), -1.0f);
}

__device__ __forceinline__ void ffma2(unsigned long long& d,
                                      unsigned long long a,
                                      unsigned long long b) {
  asm("fma.rn.f32x2 %0, %1, %2, %0;" : "+l"(d) : "l"(a), "l"(b));
}

__device__ __forceinline__ void lds2u64(unsigned long long& a,
                                        unsigned long long& b, unsigned addr) {
  asm volatile("ld.shared.v2.u64 {%0,%1}, [%2];" : "=l"(a), "=l"(b) : "r"(addr));
}

__device__ __forceinline__ void unpack2(unsigned long long v, float& lo, float& hi) {
  asm("mov.b64 {%0,%1}, %2;" : "=f"(lo), "=f"(hi) : "l"(v));
}

#define BAR_SYNC_ALL(id)   asm volatile("bar.sync %0, 576;"   :: "r"(id) : "memory")
#define BAR_ARRIVE_ALL(id) asm volatile("bar.arrive %0, 576;" :: "r"(id) : "memory")
#define BAR_GEMM()         asm volatile("bar.sync 5, 128;" ::: "memory")
// ids: FULL[b] = 1+b, EMPTY[b] = 3+b, GEMM-internal = 5

// stage W chunk (swizzled layout) via cp.async; GEMM threads only (stride 128)
__device__ __forceinline__ void stage_w(const float* __restrict__ gW1,
                                        Smem& sm, int chunk, int buf, int tid) {
  const float* src0 = gW1 + chunk * KC * H1;
  float* dst0 = &sm.W[buf * WBUFW];
  for (int seg = tid; seg < KC * 25; seg += 128) {
    int row = seg / 25, p = seg - row * 25;       // p: 16B piece (4 cols)
    int dw = row * WROW + woff(p >> 1) + (p & 1) * 4;
    unsigned d = (unsigned)__cvta_generic_to_shared(dst0 + dw);
    const float* s = src0 + row * H1 + p * 4;
    asm volatile("cp.async.ca.shared.global [%0], [%1], 16;\n" :: "r"(d), "l"(s));
  }
}
}  // namespace

__global__ void __launch_bounds__(TPB, 1)
snn_kernel(const float* __restrict__ gx, const float* __restrict__ gW1,
           const float* __restrict__ gb1, const float* __restrict__ gW2,
           const float* __restrict__ gb2, float* __restrict__ gout) {
  extern __shared__ char smraw[];
  Smem& sm = *reinterpret_cast<Smem*>(smraw);
  const int tid = threadIdx.x;
  const int rA0 = blockIdx.x * 32;

  // ---- init --------------------------------------------------------------
  for (int e = tid; e < 32 * (F / 4); e += TPB) {
    int r = e / (F / 4), s = e - r * (F / 4);
    *reinterpret_cast<float4*>(&sm.x[r * XPW + s * 4]) =
        reinterpret_cast<const float4*>(gx + (size_t)(rA0 + r) * F)[s];
  }
  for (int e = tid; e < 2 * WBUFW; e += TPB) sm.W[e] = 0.f;   // pad cols stay 0
  for (int e = tid; e < 32 * H1; e += TPB) {
    (&sm.outer[0][0])[e]  = 0.f;
    (&sm.inner1[0][0])[e] = 0.f;
  }
  for (int e = tid; e < H1 * H2; e += TPB) (&sm.W2s[0][0])[e] = gW2[e];
  for (int e = tid; e < H1; e += TPB) sm.b1s[e] = gb1[e];
  if (tid < H2) sm.b2s[tid] = gb2[tid];
  if (tid < NSTEP) {   // foldlike split: keys[t] = threefry((0,42),(0,t))
    unsigned a0, a1;
    tf2x32(0u, 42u, 0u, (unsigned)tid, a0, a1);
    sm.key0[tid] = a0; sm.key1[tid] = a1;
  }
  __syncthreads();

  if (tid < 128) {
    // =================== GEMM / layer2 half ===============================
    const int tx = tid & 15;           // col group: cols tx*8 .. tx*8+7
    const int rg = tid >> 4;           // row group: rows 4rg .. 4rg+3
    const unsigned wb0 = (unsigned)__cvta_generic_to_shared(&sm.W[0]) +
                         (unsigned)(woff(tx) * 4);
    const unsigned ab0 = (unsigned)__cvta_generic_to_shared(&sm.xit[0]) +
                         (unsigned)(rg * 32);
    // layer2 outputs: o = tid + 128*s (s<3), valid o<320; r=o/10, j=o%10
    int r2[3], j2[3]; bool ok2[3]; float i2[3], a2[3], b2r[3];
    #pragma unroll
    for (int s = 0; s < 3; ++s) {
      int o = tid + 128 * s;
      ok2[s] = o < 320;
      r2[s] = o / 10; j2[s] = o - r2[s] * 10;
      b2r[s] = ok2[s] ? sm.b2s[j2[s]] : 0.f;
      i2[s] = 0.f; a2[s] = 0.f;
    }

    stage_w(gW1, sm, 0, 0, tid);                 // prologue: chunk 0 -> buf 0
    asm volatile("cp.async.commit_group;\n");

    unsigned long long acc[4][4];
    int t = 0, c = 0;
    for (int g = 0; g < NG; ++g) {
      int nc = (c + 1 == NCH) ? 0 : c + 1;
      stage_w(gW1, sm, nc, (g + 1) & 1, tid);
      asm volatile("cp.async.commit_group;\n");
      if (c == 0) {
        #pragma unroll
        for (int r = 0; r < 4; ++r)
          #pragma unroll
          for (int p = 0; p < 4; ++p) acc[r][p] = 0ull;
      }
      asm volatile("cp.async.wait_group 1;\n");  // W[g&1] ready
      BAR_SYNC_ALL(1 + (g & 1));                 // xi[g&1] full

      const unsigned wB = wb0 + (unsigned)((g & 1) * (WBUFW * 4));
      const unsigned aB = ab0 + (unsigned)((g & 1) * (ABUF2 * 8));
      #pragma unroll 8
      for (int k = 0; k < KC; ++k) {
        unsigned long long a0, a1, a2v, a3, w01, w23, w45, w67;
        lds2u64(a0, a1,  aB + (unsigned)k * 272u);
        lds2u64(a2v, a3, aB + (unsigned)k * 272u + 16u);
        lds2u64(w01, w23, wB + (unsigned)k * 560u);
        lds2u64(w45, w67, wB + (unsigned)k * 560u + 16u);
        ffma2(acc[0][0], a0, w01);  ffma2(acc[0][1], a0, w23);
        ffma2(acc[0][2], a0, w45);  ffma2(acc[0][3], a0, w67);
        ffma2(acc[1][0], a1, w01);  ffma2(acc[1][1], a1, w23);
        ffma2(acc[1][2], a1, w45);  ffma2(acc[1][3], a1, w67);
        ffma2(acc[2][0], a2v, w01); ffma2(acc[2][1], a2v, w23);
        ffma2(acc[2][2], a2v, w45); ffma2(acc[2][3], a2v, w67);
        ffma2(acc[3][0], a3, w01);  ffma2(acc[3][1], a3, w23);
        ffma2(acc[3][2], a3, w45);  ffma2(acc[3][3], a3, w67);
      }
      BAR_ARRIVE_ALL(3 + (g & 1));               // xi[g&1] empty

      if (c == NCH - 1) {
        // ---- layer2(t): reads outer(t-1) (still intact) ----
        #pragma unroll
        for (int s = 0; s < 3; ++s) {
          if (ok2[s]) {
            float sum = 0.f;
            #pragma unroll 5
            for (int h = 0; h < H1; ++h)
              sum = fmaf(sm.outer[r2[s]][h], sm.W2s[h][j2[s]], sum);
            float exc = __fadd_rn(sum, b2r[s]);
            float in2 = __fadd_rn(exc, __fmul_rn(i2[s], 0.9f));
            float o2  = __fadd_rn(in2, -1.0f);
            float pen = __fsub_rn(in2, __fmul_rn(1.5f, in2));
            i2[s] = (o2 > 0.f) ? pen : in2;
            if (t >= 19) a2[s] = __fadd_rn(a2[s], i2[s]);
          }
        }
        BAR_GEMM();   // all layer2 reads of outer(t-1) done
        // ---- LIF-1 epilogue: write outer(t), update inner1 ----
        #pragma unroll
        for (int r = 0; r < 4; ++r) {
          int row = 4 * rg + r;
          #pragma unroll
          for (int p = 0; p < 4; ++p) {
            float lo, hi;
            unpack2(acc[r][p], lo, hi);
            #pragma unroll
            for (int hh = 0; hh < 2; ++hh) {
              int j = tx * 8 + 2 * p + hh;
              if (j < H1) {
                float val = hh ? hi : lo;
                float inn = sm.inner1[row][j];
                float exc = __fadd_rn(val, sm.b1s[j]);
                float in1 = __fadd_rn(exc, __fmul_rn(inn, 0.9f));
                float o1  = fmaxf(__fadd_rn(in1, -1.0f), 0.f);
                float pen = __fsub_rn(in1, __fmul_rn(1.5f, in1));
                sm.inner1[row][j] = (o1 > 0.f) ? pen : in1;
                sm.outer[row][j]  = o1;
              }
            }
          }
        }
        ++t;
      }
      ++c; if (c == NCH) c = 0;
    }

    // ---- final layer2(98) on outer(97) ----
    BAR_GEMM();
    #pragma unroll
    for (int s = 0; s < 3; ++s) {
      if (ok2[s]) {
        float sum = 0.f;
        #pragma unroll 5
        for (int h = 0; h < H1; ++h)
          sum = fmaf(sm.outer[r2[s]][h], sm.W2s[h][j2[s]], sum);
        float exc = __fadd_rn(sum, b2r[s]);
        float in2 = __fadd_rn(exc, __fmul_rn(i2[s], 0.9f));
        float o2  = __fadd_rn(in2, -1.0f);
        float pen = __fsub_rn(in2, __fmul_rn(1.5f, in2));
        i2[s] = (o2 > 0.f) ? pen : in2;
        a2[s] = __fadd_rn(a2[s], i2[s]);          // t=98 >= 19
        sm.outb[r2[s]][j2[s]] = a2[s];
      }
    }
  } else {
    // =================== RNG half (448 threads) ===========================
    const int rt = tid - 128;
    const float* xp[4]; float2* sp[4]; unsigned cnt0[4];
    #pragma unroll
    for (int i = 0; i < 4; ++i) {
      int idx = rt + 448 * i;                 // element in 32x56 chunk
      int row = idx / KC, kk = idx - row * KC;
      cnt0[i] = (unsigned)(rA0 + row) * 784u + (unsigned)kk;
      xp[i] = &sm.x[row * XPW + kk];
      sp[i] = &sm.xit[kk * AROW + row];       // [k][row], {v,v} dup
    }
    int t = 0, c = 0;
    for (int g = 0; g < NG; ++g) {
      int b = g & 1;
      if (g >= 2) BAR_SYNC_ALL(3 + b);        // xi[b] empty
      const unsigned kk0 = sm.key0[t], kk1 = sm.key1[t];
      const unsigned coff = (unsigned)(c * KC);
      #pragma unroll
      for (int i = 0; i < 4; ++i) {
        unsigned y0, y1;
        tf2x32(kk0, kk1, 0u, cnt0[i] + coff, y0, y1);
        float v = __fmul_rn(u01(y0 ^ y1), xp[i][c * KC]);
        sp[i][b * ABUF2] = make_float2(v, v);
      }
      BAR_ARRIVE_ALL(1 + b);                  // xi[b] full
      ++c; if (c == NCH) { c = 0; ++t; }
    }
  }

  // ---- log_softmax output ------------------------------------------------
  __syncthreads();
  if (tid < 32) {
    float v[10], m = -3.4e38f;
    #pragma unroll
    for (int j = 0; j < 10; ++j) { v[j] = sm.outb[tid][j]; m = fmaxf(m, v[j]); }
    float s = 0.f;
    #pragma unroll
    for (int j = 0; j < 10; ++j) s = __fadd_rn(s, expf(__fsub_rn(v[j], m)));
    float l = logf(s);
    #pragma unroll
    for (int j = 0; j < 10; ++j)
      gout[(rA0 + tid) * 10 + j] = __fsub_rn(__fsub_rn(v[j], m), l);
  }
}

extern "C" void kernel_launch(void* const* d_in, const int* in_sizes, int n_in,
                              void* d_out, int out_size) {
  (void)in_sizes; (void)n_in; (void)out_size;
  const float* x  = (const float*)d_in[0];
  const float* W1 = (const float*)d_in[1];
  const float* b1 = (const float*)d_in[2];
  const float* W2 = (const float*)d_in[3];
  const float* b2 = (const float*)d_in[4];
  cudaFuncSetAttribute(snn_kernel, cudaFuncAttributeMaxDynamicSharedMemorySize,
                       (int)sizeof(Smem));
  snn_kernel<<<128, TPB, sizeof(Smem)>>>(x, W1, b1, W2, b2, (float*)d_out);
}